// round 6
// baseline (speedup 1.0000x reference)
#include <cuda_runtime.h>
#include <cuda_bf16.h>

// Problem constants
#define B_   256
#define S_   2048
#define VOCAB_ 10
#define E_   32
#define H_   64
#define OUT_ 10

#define NTAB (VOCAB_ * VOCAB_)   // 100 table rows
#define CHUNK 16                  // steps per logits flush
#define NCHUNK (S_ / CHUNK)       // 128
#define HCS 68                    // hc row stride in floats (16B-aligned)

typedef unsigned long long ull;

// Scratch (no cudaMalloc allowed)
__device__ __align__(16) float g_table[NTAB * H_];     // 25.6 KB
__device__ __align__(16) unsigned char g_idx[B_ * S_]; // 512 KB

// ---- packed f32x2 helpers -------------------------------------------------
__device__ __forceinline__ void fma2(ull& acc, ull a, ull b) {
    asm("fma.rn.f32x2 %0, %1, %2, %3;" : "=l"(acc) : "l"(a), "l"(b), "l"(acc));
}
__device__ __forceinline__ ull add2(ull a, ull b) {
    ull r; asm("add.rn.f32x2 %0, %1, %2;" : "=l"(r) : "l"(a), "l"(b)); return r;
}
__device__ __forceinline__ ull pack2(float lo, float hi) {
    ull r;
    asm("mov.b64 %0, {%1, %2};" : "=l"(r)
        : "r"(__float_as_uint(lo)), "r"(__float_as_uint(hi)));
    return r;
}
__device__ __forceinline__ void unpack2(ull v, float& lo, float& hi) {
    unsigned int a, b;
    asm("mov.b64 {%0, %1}, %2;" : "=r"(a), "=r"(b) : "l"(v));
    lo = __uint_as_float(a); hi = __uint_as_float(b);
}

// Clamp-free fast tanh: 1 - 2/(e^{2x}+1).
// x->+inf: e=inf -> 1;  x->-inf: e=0 -> -1.  abs err ~5e-7.
__device__ __forceinline__ float fast_tanh(float x) {
    float e = __expf(2.0f * x);                  // FMUL + MUFU.EX2
    float r = __frcp_rn(e + 1.0f);               // FADD + MUFU/RCP
    return fmaf(-2.0f, r, 1.0f);                 // FFMA
}

// ---------------------------------------------------------------------------
// Prep kernel: blocks [0,25) build table, rest compact indices.
// ---------------------------------------------------------------------------
#define TAB_BLOCKS 25
__global__ void prep_kernel(const int* __restrict__ num1,
                            const int* __restrict__ num2,
                            const float* __restrict__ embed,
                            const float* __restrict__ Wx,
                            const float* __restrict__ bvec) {
    if (blockIdx.x < TAB_BLOCKS) {
        int i = blockIdx.x * 256 + threadIdx.x;
        if (i < NTAB * H_) {
            int v = i >> 6, j = i & 63;
            int v1 = v / VOCAB_, v2 = v % VOCAB_;
            float acc = bvec[j];
            #pragma unroll
            for (int e = 0; e < E_; ++e) {
                acc = fmaf(embed[v1 * E_ + e], Wx[e * H_ + j], acc);
                acc = fmaf(embed[v2 * E_ + e], Wx[(E_ + e) * H_ + j], acc);
            }
            g_table[i] = acc;
        }
    } else {
        int i = (blockIdx.x - TAB_BLOCKS) * 256 + threadIdx.x;
        if (i < B_ * S_) {
            g_idx[i] = (unsigned char)(num1[i] * VOCAB_ + num2[i]);
        }
    }
}

// ---------------------------------------------------------------------------
// RNN kernel: one chain per 64-thread CTA (2 warps). Thread j owns h_j.
// Per step: broadcast LDS.128 of h_prev, 32 x fma.rn.f32x2 with register
// Wh column, tree hadd, clamp-free tanh, STS.32, ONE 64-thread barrier.
// T lookups for the whole chunk preloaded into registers (off the path).
// Double 16-row history ring -> logits flush needs no extra barrier.
// ---------------------------------------------------------------------------
__global__ void __launch_bounds__(64, 2)
rnn_kernel(const float* __restrict__ Wh,
           const float* __restrict__ Wd,
           const float* __restrict__ bd,
           float* __restrict__ out) {
    __shared__ __align__(16) float T_sh[NTAB * H_];       // 25600 B
    __shared__ __align__(16) float hc[2][CHUNK * HCS];    // 8704 B double ring
    __shared__ __align__(16) ull  Wdp[OUT_ * 32];         // 2560 B packed Wd
    __shared__ float bd_sh[OUT_];

    const int tid = threadIdx.x;   // 0..63 = output index j
    const int b   = blockIdx.x;

    // cooperative smem fills
    for (int i = tid; i < NTAB * H_; i += 64) T_sh[i] = g_table[i];
    for (int i = tid; i < OUT_ * 32; i += 64) {
        int o = i >> 5, k2 = i & 31;
        Wdp[i] = pack2(Wd[(2 * k2) * OUT_ + o], Wd[(2 * k2 + 1) * OUT_ + o]);
    }
    if (tid < OUT_) bd_sh[tid] = bd[tid];

    // packed Wh column j: wkp[i] = (Wh[2i][j], Wh[2i+1][j])
    ull wkp[32];
    #pragma unroll
    for (int i = 0; i < 32; ++i) {
        wkp[i] = pack2(Wh[(2 * i) * H_ + tid], Wh[(2 * i + 1) * H_ + tid]);
    }

    // h_{-1} = 0: chunk 0 uses half 0; its t=0 reads half 1 row 15.
    hc[1][(CHUNK - 1) * HCS + tid] = 0.0f;

    const unsigned char* idx_g = &g_idx[(size_t)b * S_];
    int4 curidx = *reinterpret_cast<const int4*>(idx_g);
    __syncthreads();

    for (int c = 0; c < NCHUNK; ++c) {
        const int half  = c & 1;
        const int ohalf = half ^ 1;
        float* __restrict__ ring  = hc[half];
        const float* __restrict__ oring = hc[ohalf];

        int4 nextidx;
        if (c + 1 < NCHUNK) {
            nextidx = *reinterpret_cast<const int4*>(idx_g + (c + 1) * CHUNK);
        }
        const unsigned int packs[4] = {
            (unsigned int)curidx.x, (unsigned int)curidx.y,
            (unsigned int)curidx.z, (unsigned int)curidx.w };

        // Preload all 16 T-lookups for this chunk (independent of h).
        float tv[CHUNK];
        #pragma unroll
        for (int t = 0; t < CHUNK; ++t) {
            const int idx = (int)((packs[t >> 2] >> ((t & 3) * 8)) & 255u);
            tv[t] = T_sh[idx * H_ + tid];
        }

        #pragma unroll
        for (int t = 0; t < CHUNK; ++t) {
            // h_prev row: previous step's row, or other half's row 15 at t=0
            const float* prow = (t == 0) ? &oring[(CHUNK - 1) * HCS]
                                         : &ring[(t - 1) * HCS];
            const ulonglong2* hp = reinterpret_cast<const ulonglong2*>(prow);

            ull a0 = pack2(tv[t], 0.0f);
            ull a1 = 0, a2 = 0, a3 = 0;
            #pragma unroll
            for (int g = 0; g < 16; g += 2) {
                ulonglong2 hv0 = hp[g];
                ulonglong2 hv1 = hp[g + 1];
                fma2(a0, hv0.x, wkp[2 * g + 0]);
                fma2(a1, hv0.y, wkp[2 * g + 1]);
                fma2(a2, hv1.x, wkp[2 * g + 2]);
                fma2(a3, hv1.y, wkp[2 * g + 3]);
            }
            ull s = add2(add2(a0, a1), add2(a2, a3));
            float lo, hi; unpack2(s, lo, hi);
            float hj = fast_tanh(lo + hi);
            ring[t * HCS + tid] = hj;
            __syncthreads();
        }

        // ---- logits flush: 160 outputs, packed over k. No barrier needed:
        // next chunk writes the other ring half; 16 interleaving barriers
        // guarantee these reads drain before this half is rewritten. ----
        const int s0 = c * CHUNK;
        #pragma unroll
        for (int r = 0; r < 3; ++r) {
            int i = tid + r * 64;
            if (i < CHUNK * OUT_) {
                int t = i & 15, o = i >> 4;
                const ulonglong2* hp =
                    reinterpret_cast<const ulonglong2*>(&ring[t * HCS]);
                const ulonglong2* wp =
                    reinterpret_cast<const ulonglong2*>(&Wdp[o * 32]);
                ull a0 = pack2(bd_sh[o], 0.0f);
                ull a1 = 0;
                #pragma unroll
                for (int g = 0; g < 16; ++g) {
                    ulonglong2 hv = hp[g];
                    ulonglong2 wv = wp[g];
                    fma2(a0, hv.x, wv.x);
                    fma2(a1, hv.y, wv.y);
                }
                float lo, hi; unpack2(add2(a0, a1), lo, hi);
                out[((size_t)b * S_ + (s0 + t)) * OUT_ + o] = lo + hi;
            }
        }
        curidx = nextidx;
    }
}

// ---------------------------------------------------------------------------
// Entry point
// Inputs: num1[i32 B*S], num2[i32 B*S], embed[f32 10*32], Wx[f32 64*64],
//         Wh[f32 64*64], b[f32 64], Wd[f32 64*10], bd[f32 10]
// Output: float32 [B, S, 10]
// ---------------------------------------------------------------------------
extern "C" void kernel_launch(void* const* d_in, const int* in_sizes, int n_in,
                              void* d_out, int out_size) {
    const int*   num1  = (const int*)d_in[0];
    const int*   num2  = (const int*)d_in[1];
    const float* embed = (const float*)d_in[2];
    const float* Wx    = (const float*)d_in[3];
    const float* Wh    = (const float*)d_in[4];
    const float* bvec  = (const float*)d_in[5];
    const float* Wd    = (const float*)d_in[6];
    const float* bd    = (const float*)d_in[7];
    float* out = (float*)d_out;

    const int idx_blocks = (B_ * S_ + 255) / 256;
    prep_kernel<<<TAB_BLOCKS + idx_blocks, 256>>>(num1, num2, embed, Wx, bvec);

    rnn_kernel<<<B_, 64>>>(Wh, Wd, bd, out);
}

// round 7
// speedup vs baseline: 2.3334x; 2.3334x over previous
#include <cuda_runtime.h>
#include <cuda_bf16.h>

// Problem constants
#define B_   256
#define S_   2048
#define VOCAB_ 10
#define E_   32
#define H_   64
#define OUT_ 10

#define NTAB (VOCAB_ * VOCAB_)   // 100 table rows
#define CHUNK 16                  // steps per logits flush
#define NCHUNK (S_ / CHUNK)       // 128
#define HCS 68                    // hc row stride in floats (16B-aligned)

typedef unsigned long long ull;

// Scratch (no cudaMalloc allowed)
__device__ __align__(16) float g_table[NTAB * H_];     // 25.6 KB
__device__ __align__(16) unsigned char g_idx[B_ * S_]; // 512 KB

// ---- packed f32x2 helpers -------------------------------------------------
__device__ __forceinline__ void fma2(ull& acc, ull a, ull b) {
    asm("fma.rn.f32x2 %0, %1, %2, %3;" : "=l"(acc) : "l"(a), "l"(b), "l"(acc));
}
__device__ __forceinline__ ull add2(ull a, ull b) {
    ull r; asm("add.rn.f32x2 %0, %1, %2;" : "=l"(r) : "l"(a), "l"(b)); return r;
}
__device__ __forceinline__ ull pack2(float lo, float hi) {
    ull r;
    asm("mov.b64 %0, {%1, %2};" : "=l"(r)
        : "r"(__float_as_uint(lo)), "r"(__float_as_uint(hi)));
    return r;
}
__device__ __forceinline__ void unpack2(ull v, float& lo, float& hi) {
    unsigned int a, b;
    asm("mov.b64 {%0, %1}, %2;" : "=r"(a), "=r"(b) : "l"(v));
    lo = __uint_as_float(a); hi = __uint_as_float(b);
}

// HW tanh: single MUFU.TANH, ~16 cyc latency.
__device__ __forceinline__ float fast_tanh(float x) {
    float y;
    asm("tanh.approx.f32 %0, %1;" : "=f"(y) : "f"(x));
    return y;
}

// ---------------------------------------------------------------------------
// Prep kernel: blocks [0,25) build table, rest compact indices.
// ---------------------------------------------------------------------------
#define TAB_BLOCKS 25
__global__ void prep_kernel(const int* __restrict__ num1,
                            const int* __restrict__ num2,
                            const float* __restrict__ embed,
                            const float* __restrict__ Wx,
                            const float* __restrict__ bvec) {
    if (blockIdx.x < TAB_BLOCKS) {
        int i = blockIdx.x * 256 + threadIdx.x;
        if (i < NTAB * H_) {
            int v = i >> 6, j = i & 63;
            int v1 = v / VOCAB_, v2 = v % VOCAB_;
            float acc = bvec[j];
            #pragma unroll
            for (int e = 0; e < E_; ++e) {
                acc = fmaf(embed[v1 * E_ + e], Wx[e * H_ + j], acc);
                acc = fmaf(embed[v2 * E_ + e], Wx[(E_ + e) * H_ + j], acc);
            }
            g_table[i] = acc;
        }
    } else {
        int i = (blockIdx.x - TAB_BLOCKS) * 256 + threadIdx.x;
        if (i < B_ * S_) {
            g_idx[i] = (unsigned char)(num1[i] * VOCAB_ + num2[i]);
        }
    }
}

// ---------------------------------------------------------------------------
// RNN kernel: one chain per 64-thread CTA (2 warps). Thread j owns h_j.
// Per step: broadcast LDS.128 of h_prev, 32 x fma.rn.f32x2 with register
// Wh column, tree hadd, MUFU tanh, STS.32, ONE 64-thread barrier.
// Double 16-row history ring -> no trailing barrier at the logits flush.
// ---------------------------------------------------------------------------
__global__ void __launch_bounds__(64, 2)
rnn_kernel(const float* __restrict__ Wh,
           const float* __restrict__ Wd,
           const float* __restrict__ bd,
           float* __restrict__ out) {
    __shared__ __align__(16) float T_sh[NTAB * H_];     // 25600 B
    __shared__ __align__(16) float hc[2][CHUNK * HCS];  // 8704 B double ring
    __shared__ __align__(16) ull  Wdp[OUT_ * 32];       // 2560 B packed Wd
    __shared__ float bd_sh[OUT_];

    const int tid = threadIdx.x;   // 0..63 = output index j
    const int b   = blockIdx.x;

    // cooperative smem fills
    for (int i = tid; i < NTAB * H_; i += 64) T_sh[i] = g_table[i];
    for (int i = tid; i < OUT_ * 32; i += 64) {
        int o = i >> 5, k2 = i & 31;
        Wdp[i] = pack2(Wd[(2 * k2) * OUT_ + o], Wd[(2 * k2 + 1) * OUT_ + o]);
    }
    if (tid < OUT_) bd_sh[tid] = bd[tid];

    // packed Wh column j: wkp[i] = (Wh[2i][j], Wh[2i+1][j])
    ull wkp[32];
    #pragma unroll
    for (int i = 0; i < 32; ++i) {
        wkp[i] = pack2(Wh[(2 * i) * H_ + tid], Wh[(2 * i + 1) * H_ + tid]);
    }

    // h_{-1} = 0: chunk 0 uses half 0; its t=0 reads half 1 row 15.
    hc[1][(CHUNK - 1) * HCS + tid] = 0.0f;

    const unsigned char* idx_g = &g_idx[(size_t)b * S_];
    int4 curidx = *reinterpret_cast<const int4*>(idx_g);
    __syncthreads();

    for (int c = 0; c < NCHUNK; ++c) {
        const int half = c & 1;
        float* __restrict__ ring = hc[half];
        const float* __restrict__ oring = hc[half ^ 1];

        int4 nextidx;
        if (c + 1 < NCHUNK) {
            nextidx = *reinterpret_cast<const int4*>(idx_g + (c + 1) * CHUNK);
        }
        const unsigned int packs[4] = {
            (unsigned int)curidx.x, (unsigned int)curidx.y,
            (unsigned int)curidx.z, (unsigned int)curidx.w };

        #pragma unroll
        for (int t = 0; t < CHUNK; ++t) {
            const int idx = (int)((packs[t >> 2] >> ((t & 3) * 8)) & 255u);

            // T contribution (independent of h; LDS overlaps h row LDS)
            float tv = T_sh[idx * H_ + tid];

            // h_prev row: previous step's row, or other half's row 15 at t=0
            const float* prow = (t == 0) ? &oring[(CHUNK - 1) * HCS]
                                         : &ring[(t - 1) * HCS];
            const ulonglong2* hp = reinterpret_cast<const ulonglong2*>(prow);

            ull a0 = pack2(tv, 0.0f);
            ull a1 = 0, a2 = 0, a3 = 0;
            #pragma unroll
            for (int g = 0; g < 16; g += 2) {
                ulonglong2 hv0 = hp[g];
                ulonglong2 hv1 = hp[g + 1];
                fma2(a0, hv0.x, wkp[2 * g + 0]);
                fma2(a1, hv0.y, wkp[2 * g + 1]);
                fma2(a2, hv1.x, wkp[2 * g + 2]);
                fma2(a3, hv1.y, wkp[2 * g + 3]);
            }
            ull s = add2(add2(a0, a1), add2(a2, a3));
            float lo, hi; unpack2(s, lo, hi);
            float hj = fast_tanh(lo + hi);
            ring[t * HCS + tid] = hj;
            __syncthreads();
        }

        // ---- logits flush: 160 outputs, packed over k. No barrier needed:
        // next chunk writes the other ring half; the 16 interleaving step
        // barriers drain these reads before this half is rewritten. ----
        const int s0 = c * CHUNK;
        #pragma unroll
        for (int r = 0; r < 3; ++r) {
            int i = tid + r * 64;
            if (i < CHUNK * OUT_) {
                int t = i & 15, o = i >> 4;
                const ulonglong2* hp =
                    reinterpret_cast<const ulonglong2*>(&ring[t * HCS]);
                const ulonglong2* wp =
                    reinterpret_cast<const ulonglong2*>(&Wdp[o * 32]);
                ull a0 = pack2(bd_sh[o], 0.0f);
                ull a1 = 0;
                #pragma unroll
                for (int g = 0; g < 16; ++g) {
                    ulonglong2 hv = hp[g];
                    ulonglong2 wv = wp[g];
                    fma2(a0, hv.x, wv.x);
                    fma2(a1, hv.y, wv.y);
                }
                float lo, hi; unpack2(add2(a0, a1), lo, hi);
                out[((size_t)b * S_ + (s0 + t)) * OUT_ + o] = lo + hi;
            }
        }
        curidx = nextidx;
    }
}

// ---------------------------------------------------------------------------
// Entry point
// Inputs: num1[i32 B*S], num2[i32 B*S], embed[f32 10*32], Wx[f32 64*64],
//         Wh[f32 64*64], b[f32 64], Wd[f32 64*10], bd[f32 10]
// Output: float32 [B, S, 10]
// ---------------------------------------------------------------------------
extern "C" void kernel_launch(void* const* d_in, const int* in_sizes, int n_in,
                              void* d_out, int out_size) {
    const int*   num1  = (const int*)d_in[0];
    const int*   num2  = (const int*)d_in[1];
    const float* embed = (const float*)d_in[2];
    const float* Wx    = (const float*)d_in[3];
    const float* Wh    = (const float*)d_in[4];
    const float* bvec  = (const float*)d_in[5];
    const float* Wd    = (const float*)d_in[6];
    const float* bd    = (const float*)d_in[7];
    float* out = (float*)d_out;

    const int idx_blocks = (B_ * S_ + 255) / 256;
    prep_kernel<<<TAB_BLOCKS + idx_blocks, 256>>>(num1, num2, embed, Wx, bvec);

    rnn_kernel<<<B_, 64>>>(Wh, Wd, bd, out);
}